// round 10
// baseline (speedup 1.0000x reference)
#include <cuda_runtime.h>
#include <cuda_bf16.h>
#include <cstdint>

#define U_NUM 30000
#define NTOT  100000

typedef unsigned long long u64;
typedef unsigned int u32;

// ---------------- scratch (device globals; allocation-free) ----------------
__device__ __align__(256) float g_H0[(size_t)NTOT * 128];
__device__ __align__(256) float g_F1[(size_t)NTOT * 128];
__device__ __align__(256) float g_H1[(size_t)NTOT * 64];
__device__ __align__(256) float g_F2[(size_t)NTOT * 64];
// fragment-packed bf16 weights: uint4 = {hi01, hi23, lo01, lo23} per [ks][nt][lane]
__device__ __align__(256) uint4 g_w10f[16 * 16 * 32];
__device__ __align__(256) uint4 g_w20f[16 * 16 * 32];
__device__ __align__(256) uint4 g_w11f[8 * 8 * 32];
__device__ __align__(256) uint4 g_w21f[8 * 8 * 32];
__device__ __align__(256) uint4 g_t1f[56 * 8 * 32];

// ---------------- helpers ----------------
__device__ __forceinline__ u32 smem_u32(const void* p) {
    u32 a;
    asm("{ .reg .u64 t; cvta.to.shared.u64 t, %1; cvt.u32.u64 %0, t; }" : "=r"(a) : "l"(p));
    return a;
}
__device__ __forceinline__ void ldm4(u32* r, u32 addr) {
    asm volatile("ldmatrix.sync.aligned.m8n8.x4.shared.b16 {%0,%1,%2,%3}, [%4];"
                 : "=r"(r[0]), "=r"(r[1]), "=r"(r[2]), "=r"(r[3]) : "r"(addr));
}
__device__ __forceinline__ void mma16816(float* c, const u32* a, u32 b0, u32 b1) {
    asm volatile("mma.sync.aligned.m16n8k16.row.col.f32.bf16.bf16.f32 "
                 "{%0,%1,%2,%3}, {%4,%5,%6,%7}, {%8,%9}, {%0,%1,%2,%3};"
                 : "+f"(c[0]), "+f"(c[1]), "+f"(c[2]), "+f"(c[3])
                 : "r"(a[0]), "r"(a[1]), "r"(a[2]), "r"(a[3]), "r"(b0), "r"(b1));
}
__device__ __forceinline__ void split2(float a, float b, u32& hi, u32& lo) {
    __nv_bfloat162 h = __floats2bfloat162_rn(a, b);
    float2 hf = __bfloat1622float2(h);
    __nv_bfloat162 l = __floats2bfloat162_rn(a - hf.x, b - hf.y);
    hi = *reinterpret_cast<u32*>(&h);
    lo = *reinterpret_cast<u32*>(&l);
}
__device__ __forceinline__ u32 pack_bf2(float a, float b) {
    __nv_bfloat162 h = __floats2bfloat162_rn(a, b);
    return *reinterpret_cast<u32*>(&h);
}
__device__ __forceinline__ void red4(float* p, float a, float b, float c, float d) {
    asm volatile("{ .reg .u64 q; cvta.to.global.u64 q, %0; red.global.add.v4.f32 [q], {%1,%2,%3,%4}; }"
                 :: "l"(p), "f"(a), "f"(b), "f"(c), "f"(d) : "memory");
}

// ============================================================================
// Weight fragment prep
// ============================================================================
__device__ __forceinline__ void pack_frag(const float* __restrict__ W, uint4* __restrict__ dst,
                                          int ks, int nt, int lane, int NT, int K)
{
    int n = nt * 8 + (lane >> 2);
    int k = ks * 16 + (lane & 3) * 2;
    const float* p = W + (size_t)n * K + k;
    float x0 = p[0], x1 = p[1], x2 = p[8], x3 = p[9];
    u32 h01, l01, h23, l23;
    split2(x0, x1, h01, l01);
    split2(x2, x3, h23, l23);
    dst[((size_t)ks * NT + nt) * 32 + lane] = make_uint4(h01, h23, l01, l23);
}

__global__ void k_prep(const float* __restrict__ W10, const float* __restrict__ W20,
                       const float* __restrict__ W11, const float* __restrict__ W21,
                       const float* __restrict__ T1W)
{
    int i = blockIdx.x * 256 + threadIdx.x;
    if (i < 8192) {                        // layer0: KS=16, NT=16
        int lane = i & 31, nt = (i >> 5) & 15, ks = i >> 9;
        pack_frag(W10, g_w10f, ks, nt, lane, 16, 256);
        pack_frag(W20, g_w20f, ks, nt, lane, 16, 256);
    } else if (i < 10240) {                // layer1: KS=8, NT=8
        int j = i - 8192;
        int lane = j & 31, nt = (j >> 5) & 7, ks = j >> 8;
        pack_frag(W11, g_w11f, ks, nt, lane, 8, 128);
        pack_frag(W21, g_w21f, ks, nt, lane, 8, 128);
    } else if (i < 24576) {                // T1: KS=56, NT=8
        int j = i - 10240;
        int lane = j & 31, nt = (j >> 5) & 7, ks = j >> 8;
        pack_frag(T1W, g_t1f, ks, nt, lane, 8, 896);
    }
}

// ============================================================================
// Split single-output GEMM (weights/buffers selected IN-KERNEL from globals):
//  SQUARE=0 (main, bf16x3): F = A@W1^T + (b1+b2);  H = A@W1^T  (overwrite)
//  SQUARE=1 (square, bf16): H += (A*A)@W2^T        (read-modify-write)
// MODE 0: A = concat(uE,iE) [N,KTOT], DOUT=128; MODE 1: A = g_F1 [N,128], DOUT=64.
// ============================================================================
template<int THREADS, int OCC, int BM, int DOUT, int KTOT, int CHUNK,
         int MODE, int SQUARE, int WM_N, int WN_N>
__global__ __launch_bounds__(THREADS, OCC) void k_g(
    const float* __restrict__ uE, const float* __restrict__ iE,
    const float* __restrict__ b1, const float* __restrict__ b2)
{
    constexpr int SR = CHUNK + 8;
    constexpr int ABUF = BM * SR;
    constexpr int NCH = KTOT / CHUNK;
    constexpr int KS_C = CHUNK / 16;
    constexpr int NT = DOUT / 8;
    constexpr int JW = NT / WN_N;
    constexpr int NVAR = SQUARE ? 1 : 2;
    constexpr int F4R = CHUNK / 4;
    extern __shared__ __align__(16) char smem[];
    __nv_bfloat16* sA = (__nv_bfloat16*)smem;
    const u32 sbase = smem_u32(smem);

    // device-side global selection (host cannot take __device__ addresses!)
    const uint4* __restrict__ wf =
        (MODE == 0) ? (SQUARE ? g_w20f : g_w10f)
                    : (SQUARE ? g_w21f : g_w11f);
    float* __restrict__ Fout = (MODE == 0) ? g_F1 : g_F2;
    float* __restrict__ Hout = (MODE == 0) ? g_H0 : g_H1;

    const int t = threadIdx.x, wid = t >> 5, lane = t & 31;
    const int wm = wid / WN_N, wn = wid % WN_N;
    const int row0 = blockIdx.x * BM;

    float acc[2][JW][4];
#pragma unroll
    for (int mt = 0; mt < 2; mt++)
#pragma unroll
        for (int j = 0; j < JW; j++)
#pragma unroll
            for (int q = 0; q < 4; q++) acc[mt][j][q] = 0.f;

    const int arow = lane & 15;
    const int kshift = (lane >> 4) * 8;

    for (int ch = 0; ch < NCH; ch++) {
        __syncthreads();
        // ---- stage A chunk ----
#pragma unroll
        for (int it = 0; it < BM * F4R / THREADS; it++) {
            int fid = t + it * THREADS;
            int r = fid / F4R;
            int c4 = (fid % F4R) * 4;
            int gr = row0 + r;
            float4 v = make_float4(0.f, 0.f, 0.f, 0.f);
            if (gr < NTOT) {
                const float* src;
                if (MODE == 0) src = (gr < U_NUM) ? uE + (size_t)gr * 256
                                                  : iE + (size_t)(gr - U_NUM) * 256;
                else           src = g_F1 + (size_t)gr * 128;
                v = *(const float4*)(src + ch * CHUNK + c4);
            }
            int off = r * SR + c4;
            if (SQUARE) {
                *(uint2*)(sA + off) = make_uint2(pack_bf2(v.x * v.x, v.y * v.y),
                                                 pack_bf2(v.z * v.z, v.w * v.w));
            } else {
                u32 h01, l01, h23, l23;
                split2(v.x, v.y, h01, l01);
                split2(v.z, v.w, h23, l23);
                *(uint2*)(sA + off)        = make_uint2(h01, h23);
                *(uint2*)(sA + ABUF + off) = make_uint2(l01, l23);
            }
        }
        __syncthreads();

#pragma unroll 2
        for (int ks2 = 0; ks2 < KS_C; ks2++) {
            const int ks = ch * KS_C + ks2;
            u32 a[NVAR][2][4];
#pragma unroll
            for (int v = 0; v < NVAR; v++)
#pragma unroll
                for (int mt = 0; mt < 2; mt++) {
                    int row = wm * 32 + mt * 16 + arow;
                    u32 addr = sbase + (u32)((v * ABUF + row * SR + ks2 * 16 + kshift) * 2);
                    ldm4(a[v][mt], addr);
                }
#pragma unroll
            for (int j = 0; j < JW; j++) {
                int nt = wn * JW + j;
                u32 idx = ((u32)(ks * NT + nt)) * 32 + lane;
                if (SQUARE) {
                    uint2 bw = __ldg((const uint2*)wf + (size_t)idx * 2);  // hi half
#pragma unroll
                    for (int mt = 0; mt < 2; mt++)
                        mma16816(acc[mt][j], a[0][mt], bw.x, bw.y);
                } else {
                    uint4 bw = __ldg(wf + idx);
#pragma unroll
                    for (int mt = 0; mt < 2; mt++) {
                        mma16816(acc[mt][j], a[0][mt], bw.x, bw.y);
                        mma16816(acc[mt][j], a[0][mt], bw.z, bw.w);
                        mma16816(acc[mt][j], a[1][mt], bw.x, bw.y);
                    }
                }
            }
        }
    }

    // ---- epilogue ----
    const int r_base = row0 + wm * 32 + (lane >> 2);
    const int c_base = wn * (JW * 8) + (lane & 3) * 2;
#pragma unroll
    for (int mt = 0; mt < 2; mt++)
#pragma unroll
        for (int j = 0; j < JW; j++) {
            int c = c_base + j * 8;
            float bs0 = 0.f, bs1 = 0.f;
            if (!SQUARE) {
                bs0 = __ldg(b1 + c) + __ldg(b2 + c);
                bs1 = __ldg(b1 + c + 1) + __ldg(b2 + c + 1);
            }
#pragma unroll
            for (int half = 0; half < 2; half++) {
                int r = r_base + mt * 16 + half * 8;
                if (r < NTOT) {
                    float a0 = acc[mt][j][half * 2], a1 = acc[mt][j][half * 2 + 1];
                    float* hp = Hout + (size_t)r * DOUT + c;
                    if (SQUARE) {
                        float2 old = *(float2*)hp;
                        *(float2*)hp = make_float2(old.x + a0, old.y + a1);
                    } else {
                        *(float2*)(Fout + (size_t)r * DOUT + c) = make_float2(a0 + bs0, a1 + bs1);
                        *(float2*)hp = make_float2(a0, a1);
                    }
                }
            }
        }
}

// ============================================================================
// SpMM scatter: F[row] += val * H[col].  4 edges per (sub)warp.
// ============================================================================
__global__ void k_spmm128(const int* __restrict__ er, const int* __restrict__ ec,
                          const float* __restrict__ ev, int nnz)
{
    int w = (blockIdx.x * blockDim.x + threadIdx.x) >> 5;
    int lane = threadIdx.x & 31;
    int e0 = w * 4;
    if (e0 >= nnz) return;
    if (e0 + 4 <= nnz) {
        int4 r = *(const int4*)(er + e0);
        int4 c = *(const int4*)(ec + e0);
        float4 v = *(const float4*)(ev + e0);
        float4 x0 = *(const float4*)(g_H0 + (size_t)c.x * 128 + lane * 4);
        float4 x1 = *(const float4*)(g_H0 + (size_t)c.y * 128 + lane * 4);
        float4 x2 = *(const float4*)(g_H0 + (size_t)c.z * 128 + lane * 4);
        float4 x3 = *(const float4*)(g_H0 + (size_t)c.w * 128 + lane * 4);
        red4(g_F1 + (size_t)r.x * 128 + lane * 4, v.x * x0.x, v.x * x0.y, v.x * x0.z, v.x * x0.w);
        red4(g_F1 + (size_t)r.y * 128 + lane * 4, v.y * x1.x, v.y * x1.y, v.y * x1.z, v.y * x1.w);
        red4(g_F1 + (size_t)r.z * 128 + lane * 4, v.z * x2.x, v.z * x2.y, v.z * x2.z, v.z * x2.w);
        red4(g_F1 + (size_t)r.w * 128 + lane * 4, v.w * x3.x, v.w * x3.y, v.w * x3.z, v.w * x3.w);
    } else {
        for (int e = e0; e < nnz; e++) {
            int r = __ldg(er + e), c = __ldg(ec + e);
            float v = __ldg(ev + e);
            float4 x = *(const float4*)(g_H0 + (size_t)c * 128 + lane * 4);
            red4(g_F1 + (size_t)r * 128 + lane * 4, v * x.x, v * x.y, v * x.z, v * x.w);
        }
    }
}

__global__ void k_spmm64(const int* __restrict__ er, const int* __restrict__ ec,
                         const float* __restrict__ ev, int nnz)
{
    int idx = blockIdx.x * blockDim.x + threadIdx.x;
    int hw = idx >> 4;
    int l = idx & 15;
    int e0 = hw * 4;
    if (e0 >= nnz) return;
    if (e0 + 4 <= nnz) {
        int4 r = *(const int4*)(er + e0);
        int4 c = *(const int4*)(ec + e0);
        float4 v = *(const float4*)(ev + e0);
        float4 x0 = *(const float4*)(g_H1 + (size_t)c.x * 64 + l * 4);
        float4 x1 = *(const float4*)(g_H1 + (size_t)c.y * 64 + l * 4);
        float4 x2 = *(const float4*)(g_H1 + (size_t)c.z * 64 + l * 4);
        float4 x3 = *(const float4*)(g_H1 + (size_t)c.w * 64 + l * 4);
        red4(g_F2 + (size_t)r.x * 64 + l * 4, v.x * x0.x, v.x * x0.y, v.x * x0.z, v.x * x0.w);
        red4(g_F2 + (size_t)r.y * 64 + l * 4, v.y * x1.x, v.y * x1.y, v.y * x1.z, v.y * x1.w);
        red4(g_F2 + (size_t)r.z * 64 + l * 4, v.z * x2.x, v.z * x2.y, v.z * x2.z, v.z * x2.w);
        red4(g_F2 + (size_t)r.w * 64 + l * 4, v.w * x3.x, v.w * x3.y, v.w * x3.z, v.w * x3.w);
    } else {
        for (int e = e0; e < nnz; e++) {
            int r = __ldg(er + e), c = __ldg(ec + e);
            float v = __ldg(ev + e);
            float4 x = *(const float4*)(g_H1 + (size_t)c * 64 + l * 4);
            red4(g_F2 + (size_t)r * 64 + l * 4, v * x.x, v * x.y, v * x.z, v * x.w);
        }
    }
}

// ============================================================================
// Fused MLP head: layer1 (896->64) bf16x3 mma, layers 2/3 FFMA.
// ============================================================================
__global__ __launch_bounds__(256, 2) void k_mlp_mma(
    const int* __restrict__ uIdx, const int* __restrict__ itIdx,
    const float* __restrict__ uE, const float* __restrict__ iE,
    const float* __restrict__ T1b,
    const float* __restrict__ T2W, const float* __restrict__ T2b,
    const float* __restrict__ T3W, const float* __restrict__ T3b,
    float* __restrict__ out, int B)
{
    constexpr int SR = 232;
    constexpr int ABUF = 64 * SR;
    constexpr int OFF_SU = 2 * ABUF * 2;
    constexpr int OFF_SI = OFF_SU + 256;
    constexpr int HSR = 65;
    constexpr int OFF_T2 = 64 * HSR * 4 + 64;
    constexpr int OFF_PART = OFF_T2 + 32 * 64 * 4;
    extern __shared__ __align__(16) char smem[];
    __nv_bfloat16* sA = (__nv_bfloat16*)smem;
    const u32 sbase = smem_u32(smem);
    int* su = (int*)(smem + OFF_SU);
    int* si = (int*)(smem + OFF_SI);

    const int t = threadIdx.x, wid = t >> 5, lane = t & 31;
    const int wm = wid >> 2, wn = wid & 3;
    const int rb = blockIdx.x * 64;

    if (t < 64) {
        int br = rb + t;
        su[t] = (br < B) ? uIdx[br] : 0;
        si[t] = (br < B) ? itIdx[br] : 0;
    }

    float acc[2][2][4];
#pragma unroll
    for (int mt = 0; mt < 2; mt++)
#pragma unroll
        for (int j = 0; j < 2; j++)
#pragma unroll
            for (int q = 0; q < 4; q++) acc[mt][j][q] = 0.f;

    const int arow = lane & 15;
    const int kshift = (lane >> 4) * 8;

    for (int chunk = 0; chunk < 4; chunk++) {
        const int kb = chunk * 224;
        __syncthreads();
#pragma unroll
        for (int it = 0; it < 14; it++) {
            int fid = t + it * 256;
            int r = fid / 56;
            int c4 = (fid % 56) * 4;
            int kg = kb + c4;
            const float* src; int stride, off, rowi;
            if (kg < 256)      { src = uE;   stride = 256; off = kg;       rowi = su[r]; }
            else if (kg < 384) { src = g_F1; stride = 128; off = kg - 256; rowi = su[r]; }
            else if (kg < 448) { src = g_F2; stride = 64;  off = kg - 384; rowi = su[r]; }
            else if (kg < 704) { src = iE;   stride = 256; off = kg - 448; rowi = si[r]; }
            else if (kg < 832) { src = g_F1; stride = 128; off = kg - 704; rowi = si[r] + U_NUM; }
            else               { src = g_F2; stride = 64;  off = kg - 832; rowi = si[r] + U_NUM; }
            float4 v = *(const float4*)(src + (size_t)rowi * stride + off);
            u32 h01, l01, h23, l23;
            split2(v.x, v.y, h01, l01);
            split2(v.z, v.w, h23, l23);
            int so = r * SR + c4;
            *(uint2*)(sA + so)        = make_uint2(h01, h23);
            *(uint2*)(sA + ABUF + so) = make_uint2(l01, l23);
        }
        __syncthreads();

#pragma unroll 2
        for (int ks2 = 0; ks2 < 14; ks2++) {
            const int ks = chunk * 14 + ks2;
            uint4 bw[2];
#pragma unroll
            for (int j = 0; j < 2; j++) {
                int nt = wn * 2 + j;
                bw[j] = __ldg(g_t1f + ((u32)(ks * 8 + nt)) * 32 + lane);
            }
            u32 a[2][2][4];
#pragma unroll
            for (int v = 0; v < 2; v++)
#pragma unroll
                for (int mt = 0; mt < 2; mt++) {
                    int row = wm * 32 + mt * 16 + arow;
                    u32 addr = sbase + (u32)((v * ABUF + row * SR + ks2 * 16 + kshift) * 2);
                    ldm4(a[v][mt], addr);
                }
#pragma unroll
            for (int mt = 0; mt < 2; mt++)
#pragma unroll
                for (int j = 0; j < 2; j++) {
                    mma16816(acc[mt][j], a[0][mt], bw[j].x, bw[j].y);
                    mma16816(acc[mt][j], a[0][mt], bw[j].z, bw[j].w);
                    mma16816(acc[mt][j], a[1][mt], bw[j].x, bw[j].y);
                }
        }
    }
    __syncthreads();

    float* Hs = (float*)smem;
    float* T2s = (float*)(smem + OFF_T2);
    float* part = (float*)(smem + OFF_PART);
    {
        const int rr = wm * 32 + (lane >> 2);
        const int cc = wn * 16 + (lane & 3) * 2;
#pragma unroll
        for (int mt = 0; mt < 2; mt++)
#pragma unroll
            for (int j = 0; j < 2; j++) {
                int c = cc + j * 8;
                float tb0 = __ldg(T1b + c), tb1 = __ldg(T1b + c + 1);
#pragma unroll
                for (int half = 0; half < 2; half++) {
                    int r = rr + mt * 16 + half * 8;
                    Hs[r * HSR + c]     = fmaxf(acc[mt][j][half * 2] + tb0, 0.f);
                    Hs[r * HSR + c + 1] = fmaxf(acc[mt][j][half * 2 + 1] + tb1, 0.f);
                }
            }
    }
#pragma unroll
    for (int i = 0; i < 2; i++) {
        int idx = t + i * 256;
        ((float4*)T2s)[idx] = ((const float4*)T2W)[idx];
    }
    __syncthreads();

    {
        int r = t & 63, g = t >> 6;
        float p = 0.f;
#pragma unroll
        for (int j = 0; j < 8; j++) {
            int c2 = g * 8 + j;
            float s = T2b[c2];
#pragma unroll
            for (int k = 0; k < 64; k++) s += Hs[r * HSR + k] * T2s[c2 * 64 + k];
            p += fmaxf(s, 0.f) * T3W[c2];
        }
        part[g * 64 + r] = p;
    }
    __syncthreads();
    if (t < 64) {
        int br = rb + t;
        if (br < B)
            out[br] = part[t] + part[64 + t] + part[128 + t] + part[192 + t] + T3b[0];
    }
}

// ============================================================================
extern "C" void kernel_launch(void* const* d_in, const int* in_sizes, int n_in,
                              void* d_out, int out_size)
{
    const int*   userIdx = (const int*)d_in[0];
    const int*   itemIdx = (const int*)d_in[1];
    const int*   er      = (const int*)d_in[2];
    const int*   ec      = (const int*)d_in[3];
    const float* ev      = (const float*)d_in[4];
    const float* uE      = (const float*)d_in[5];
    const float* iE      = (const float*)d_in[6];
    const float* W1_0    = (const float*)d_in[7];
    const float* b1_0    = (const float*)d_in[8];
    const float* W2_0    = (const float*)d_in[9];
    const float* b2_0    = (const float*)d_in[10];
    const float* W1_1    = (const float*)d_in[11];
    const float* b1_1    = (const float*)d_in[12];
    const float* W2_1    = (const float*)d_in[13];
    const float* b2_1    = (const float*)d_in[14];
    const float* T1W     = (const float*)d_in[15];
    const float* T1b     = (const float*)d_in[16];
    const float* T2W     = (const float*)d_in[17];
    const float* T2b     = (const float*)d_in[18];
    const float* T3W     = (const float*)d_in[19];
    const float* T3b     = (const float*)d_in[20];
    float* out = (float*)d_out;

    const int B   = in_sizes[0];
    const int nnz = in_sizes[2];

    constexpr int SMEM0M = 2 * 64 * (128 + 8) * 2;   // 34816
    constexpr int SMEM0S = 1 * 64 * (128 + 8) * 2;   // 17408
    constexpr int SMEM1M = 2 * 64 * (64 + 8) * 2;    // 18432
    constexpr int SMEM1S = 1 * 64 * (64 + 8) * 2;    // 9216
    constexpr int SMEMM = 2 * 64 * 232 * 2 + 1024;   // 60416
    static bool attr_done = false;
    if (!attr_done) {
        cudaFuncSetAttribute((const void*)k_g<256, 3, 64, 128, 256, 128, 0, 0, 2, 4>,
                             cudaFuncAttributeMaxDynamicSharedMemorySize, SMEM0M);
        cudaFuncSetAttribute((const void*)k_g<256, 4, 64, 128, 256, 128, 0, 1, 2, 4>,
                             cudaFuncAttributeMaxDynamicSharedMemorySize, SMEM0S);
        cudaFuncSetAttribute((const void*)k_g<128, 6, 64, 64, 128, 64, 1, 0, 2, 2>,
                             cudaFuncAttributeMaxDynamicSharedMemorySize, SMEM1M);
        cudaFuncSetAttribute((const void*)k_g<128, 8, 64, 64, 128, 64, 1, 1, 2, 2>,
                             cudaFuncAttributeMaxDynamicSharedMemorySize, SMEM1S);
        cudaFuncSetAttribute((const void*)k_mlp_mma,
                             cudaFuncAttributeMaxDynamicSharedMemorySize, SMEMM);
        attr_done = true;
    }

    const int gb = (NTOT + 63) / 64;   // 1563

    k_prep<<<96, 256>>>(W1_0, W2_0, W1_1, W2_1, T1W);

    // layer 0: main (F1 = G1+bias, H0 = G1), then square (H0 += G2)
    k_g<256, 3, 64, 128, 256, 128, 0, 0, 2, 4><<<gb, 256, SMEM0M>>>(uE, iE, b1_0, b2_0);
    k_g<256, 4, 64, 128, 256, 128, 0, 1, 2, 4><<<gb, 256, SMEM0S>>>(uE, iE, b1_0, b2_0);

    {
        long long warps = ((long long)nnz + 3) / 4;
        int blocks = (int)((warps * 32 + 255) / 256);
        k_spmm128<<<blocks, 256>>>(er, ec, ev, nnz);
    }

    // layer 1
    k_g<128, 6, 64, 64, 128, 64, 1, 0, 2, 2><<<gb, 128, SMEM1M>>>(uE, iE, b1_1, b2_1);
    k_g<128, 8, 64, 64, 128, 64, 1, 1, 2, 2><<<gb, 128, SMEM1S>>>(uE, iE, b1_1, b2_1);

    {
        long long hws = ((long long)nnz + 3) / 4;
        int blocks = (int)((hws * 16 + 255) / 256);
        k_spmm64<<<blocks, 256>>>(er, ec, ev, nnz);
    }

    k_mlp_mma<<<(B + 63) / 64, 256, SMEMM>>>(userIdx, itemIdx, uE, iE,
                                             T1b, T2W, T2b, T3W, T3b, out, B);
}

// round 11
// speedup vs baseline: 1.2865x; 1.2865x over previous
#include <cuda_runtime.h>
#include <cuda_bf16.h>
#include <cstdint>

#define U_NUM 30000
#define NTOT  100000

typedef unsigned long long u64;
typedef unsigned int u32;

// ---------------- scratch (device globals; allocation-free) ----------------
__device__ __align__(256) float g_H0[(size_t)NTOT * 128];
__device__ __align__(256) float g_F1[(size_t)NTOT * 128];
__device__ __align__(256) float g_H1[(size_t)NTOT * 64];
__device__ __align__(256) float g_F2[(size_t)NTOT * 64];
// fragment-packed bf16 weights: uint4 = {hi01, hi23, lo01, lo23} per [ks][nt][lane]
__device__ __align__(256) uint4 g_w10f[16 * 16 * 32];
__device__ __align__(256) uint4 g_w20f[16 * 16 * 32];
__device__ __align__(256) uint4 g_w11f[8 * 8 * 32];
__device__ __align__(256) uint4 g_w21f[8 * 8 * 32];
__device__ __align__(256) uint4 g_t1f[56 * 8 * 32];

// ---------------- helpers ----------------
__device__ __forceinline__ u32 smem_u32(const void* p) {
    u32 a;
    asm("{ .reg .u64 t; cvta.to.shared.u64 t, %1; cvt.u32.u64 %0, t; }" : "=r"(a) : "l"(p));
    return a;
}
__device__ __forceinline__ void ldm4(u32* r, u32 addr) {
    asm volatile("ldmatrix.sync.aligned.m8n8.x4.shared.b16 {%0,%1,%2,%3}, [%4];"
                 : "=r"(r[0]), "=r"(r[1]), "=r"(r[2]), "=r"(r[3]) : "r"(addr));
}
__device__ __forceinline__ void mma16816(float* c, const u32* a, u32 b0, u32 b1) {
    asm volatile("mma.sync.aligned.m16n8k16.row.col.f32.bf16.bf16.f32 "
                 "{%0,%1,%2,%3}, {%4,%5,%6,%7}, {%8,%9}, {%0,%1,%2,%3};"
                 : "+f"(c[0]), "+f"(c[1]), "+f"(c[2]), "+f"(c[3])
                 : "r"(a[0]), "r"(a[1]), "r"(a[2]), "r"(a[3]), "r"(b0), "r"(b1));
}
__device__ __forceinline__ void split2(float a, float b, u32& hi, u32& lo) {
    __nv_bfloat162 h = __floats2bfloat162_rn(a, b);
    float2 hf = __bfloat1622float2(h);
    __nv_bfloat162 l = __floats2bfloat162_rn(a - hf.x, b - hf.y);
    hi = *reinterpret_cast<u32*>(&h);
    lo = *reinterpret_cast<u32*>(&l);
}
__device__ __forceinline__ u32 sq_bf16x2(u32 x) {
    __nv_bfloat162 h = *reinterpret_cast<__nv_bfloat162*>(&x);
    __nv_bfloat162 s = __hmul2(h, h);
    return *reinterpret_cast<u32*>(&s);
}
__device__ __forceinline__ void red4(float* p, float a, float b, float c, float d) {
    asm volatile("{ .reg .u64 q; cvta.to.global.u64 q, %0; red.global.add.v4.f32 [q], {%1,%2,%3,%4}; }"
                 :: "l"(p), "f"(a), "f"(b), "f"(c), "f"(d) : "memory");
}

// ============================================================================
// Weight fragment prep
// ============================================================================
__device__ __forceinline__ void pack_frag(const float* __restrict__ W, uint4* __restrict__ dst,
                                          int ks, int nt, int lane, int NT, int K)
{
    int n = nt * 8 + (lane >> 2);
    int k = ks * 16 + (lane & 3) * 2;
    const float* p = W + (size_t)n * K + k;
    float x0 = p[0], x1 = p[1], x2 = p[8], x3 = p[9];
    u32 h01, l01, h23, l23;
    split2(x0, x1, h01, l01);
    split2(x2, x3, h23, l23);
    dst[((size_t)ks * NT + nt) * 32 + lane] = make_uint4(h01, h23, l01, l23);
}

__global__ void k_prep(const float* __restrict__ W10, const float* __restrict__ W20,
                       const float* __restrict__ W11, const float* __restrict__ W21,
                       const float* __restrict__ T1W)
{
    int i = blockIdx.x * 256 + threadIdx.x;
    if (i < 8192) {                        // layer0: KS=16, NT=16
        int lane = i & 31, nt = (i >> 5) & 15, ks = i >> 9;
        pack_frag(W10, g_w10f, ks, nt, lane, 16, 256);
        pack_frag(W20, g_w20f, ks, nt, lane, 16, 256);
    } else if (i < 10240) {                // layer1: KS=8, NT=8
        int j = i - 8192;
        int lane = j & 31, nt = (j >> 5) & 7, ks = j >> 8;
        pack_frag(W11, g_w11f, ks, nt, lane, 8, 128);
        pack_frag(W21, g_w21f, ks, nt, lane, 8, 128);
    } else if (i < 24576) {                // T1: KS=56, NT=8
        int j = i - 10240;
        int lane = j & 31, nt = (j >> 5) & 7, ks = j >> 8;
        pack_frag(T1W, g_t1f, ks, nt, lane, 8, 896);
    }
}

// ============================================================================
// Fused dual GEMM: main path bf16x3 compensated; square path's A fragment is
// derived IN REGISTERS as elementwise square of the hi fragment (HMUL2.BF16)
// — no square staging buffer, no extra ldmatrix.
//   Fout = A@W1^T + (b1+b2),  Hout = A@W1^T + (A*A)@W2^T
// ============================================================================
template<int THREADS, int OCC, int BM, int DOUT, int KTOT, int CHUNK,
         int MODE, int WM_N, int WN_N>
__global__ __launch_bounds__(THREADS, OCC) void k_gemm_mma(
    const float* __restrict__ uE, const float* __restrict__ iE,
    const float* __restrict__ b1, const float* __restrict__ b2)
{
    constexpr int SR = CHUNK + 8;
    constexpr int ABUF = BM * SR;          // bf16 elements per variant
    constexpr int NCH = KTOT / CHUNK;
    constexpr int KS_C = CHUNK / 16;
    constexpr int NT = DOUT / 8;
    constexpr int JW = NT / WN_N;
    constexpr int F4R = CHUNK / 4;
    extern __shared__ __align__(16) char smem[];
    __nv_bfloat16* sA = (__nv_bfloat16*)smem;
    const u32 sbase = smem_u32(smem);

    const uint4* __restrict__ w1f = (MODE == 0) ? g_w10f : g_w11f;
    const uint2* __restrict__ w2f = (MODE == 0) ? (const uint2*)g_w20f : (const uint2*)g_w21f;
    float* __restrict__ Fout = (MODE == 0) ? g_F1 : g_F2;
    float* __restrict__ Hout = (MODE == 0) ? g_H0 : g_H1;

    const int t = threadIdx.x, wid = t >> 5, lane = t & 31;
    const int wm = wid / WN_N, wn = wid % WN_N;
    const int row0 = blockIdx.x * BM;

    float acc1[2][JW][4], acc2[2][JW][4];
#pragma unroll
    for (int mt = 0; mt < 2; mt++)
#pragma unroll
        for (int j = 0; j < JW; j++)
#pragma unroll
            for (int q = 0; q < 4; q++) { acc1[mt][j][q] = 0.f; acc2[mt][j][q] = 0.f; }

    const int arow = lane & 15;
    const int kshift = (lane >> 4) * 8;

    for (int ch = 0; ch < NCH; ch++) {
        __syncthreads();
        // ---- stage A chunk: fp32 -> {hi, lo} bf16 (square derived later) ----
#pragma unroll
        for (int it = 0; it < BM * F4R / THREADS; it++) {
            int fid = t + it * THREADS;
            int r = fid / F4R;
            int c4 = (fid % F4R) * 4;
            int gr = row0 + r;
            float4 v = make_float4(0.f, 0.f, 0.f, 0.f);
            if (gr < NTOT) {
                const float* src;
                if (MODE == 0) src = (gr < U_NUM) ? uE + (size_t)gr * 256
                                                  : iE + (size_t)(gr - U_NUM) * 256;
                else           src = g_F1 + (size_t)gr * 128;
                v = *(const float4*)(src + ch * CHUNK + c4);
            }
            u32 h01, l01, h23, l23;
            split2(v.x, v.y, h01, l01);
            split2(v.z, v.w, h23, l23);
            int off = r * SR + c4;
            *(uint2*)(sA + off)        = make_uint2(h01, h23);
            *(uint2*)(sA + ABUF + off) = make_uint2(l01, l23);
        }
        __syncthreads();

#pragma unroll 2
        for (int ks2 = 0; ks2 < KS_C; ks2++) {
            const int ks = ch * KS_C + ks2;
            // A fragments via ldmatrix (hi, lo); square fragment in registers
            u32 a[2][2][4];
#pragma unroll
            for (int v = 0; v < 2; v++)
#pragma unroll
                for (int mt = 0; mt < 2; mt++) {
                    int row = wm * 32 + mt * 16 + arow;
                    u32 addr = sbase + (u32)((v * ABUF + row * SR + ks2 * 16 + kshift) * 2);
                    ldm4(a[v][mt], addr);
                }
            u32 asq[2][4];
#pragma unroll
            for (int mt = 0; mt < 2; mt++)
#pragma unroll
                for (int i = 0; i < 4; i++)
                    asq[mt][i] = sq_bf16x2(a[0][mt][i]);

            // B fragments in j-halves
#pragma unroll
            for (int h = 0; h < (JW + 1) / 2; h++) {
                constexpr int JH = (JW >= 2) ? 2 : 1;
                uint4 bw1[JH];
                uint2 bw2[JH];
#pragma unroll
                for (int jj = 0; jj < JH; jj++) {
                    int nt = wn * JW + h * JH + jj;
                    u32 idx = ((u32)(ks * NT + nt)) * 32 + lane;
                    bw1[jj] = __ldg(w1f + idx);
                    bw2[jj] = __ldg(w2f + (size_t)idx * 2);   // hi half only
                }
#pragma unroll
                for (int mt = 0; mt < 2; mt++)
#pragma unroll
                    for (int jj = 0; jj < JH; jj++) {
                        int j = h * JH + jj;
                        mma16816(acc1[mt][j], a[0][mt], bw1[jj].x, bw1[jj].y);
                        mma16816(acc1[mt][j], a[0][mt], bw1[jj].z, bw1[jj].w);
                        mma16816(acc1[mt][j], a[1][mt], bw1[jj].x, bw1[jj].y);
                        mma16816(acc2[mt][j], asq[mt],  bw2[jj].x, bw2[jj].y);
                    }
            }
        }
    }

    // ---- epilogue ----
    const int r_base = row0 + wm * 32 + (lane >> 2);
    const int c_base = wn * (JW * 8) + (lane & 3) * 2;
#pragma unroll
    for (int mt = 0; mt < 2; mt++)
#pragma unroll
        for (int j = 0; j < JW; j++) {
            int c = c_base + j * 8;
            float bs0 = __ldg(b1 + c) + __ldg(b2 + c);
            float bs1 = __ldg(b1 + c + 1) + __ldg(b2 + c + 1);
#pragma unroll
            for (int half = 0; half < 2; half++) {
                int r = r_base + mt * 16 + half * 8;
                if (r < NTOT) {
                    float a0 = acc1[mt][j][half * 2], a1 = acc1[mt][j][half * 2 + 1];
                    float2 f = make_float2(a0 + bs0, a1 + bs1);
                    float2 h2 = make_float2(a0 + acc2[mt][j][half * 2],
                                            a1 + acc2[mt][j][half * 2 + 1]);
                    *(float2*)(Fout + (size_t)r * DOUT + c) = f;
                    *(float2*)(Hout + (size_t)r * DOUT + c) = h2;
                }
            }
        }
}

// ============================================================================
// SpMM scatter: F[row] += val * H[col].  4 edges per (sub)warp.
// ============================================================================
__global__ void k_spmm128(const int* __restrict__ er, const int* __restrict__ ec,
                          const float* __restrict__ ev, int nnz)
{
    int w = (blockIdx.x * blockDim.x + threadIdx.x) >> 5;
    int lane = threadIdx.x & 31;
    int e0 = w * 4;
    if (e0 >= nnz) return;
    if (e0 + 4 <= nnz) {
        int4 r = *(const int4*)(er + e0);
        int4 c = *(const int4*)(ec + e0);
        float4 v = *(const float4*)(ev + e0);
        float4 x0 = *(const float4*)(g_H0 + (size_t)c.x * 128 + lane * 4);
        float4 x1 = *(const float4*)(g_H0 + (size_t)c.y * 128 + lane * 4);
        float4 x2 = *(const float4*)(g_H0 + (size_t)c.z * 128 + lane * 4);
        float4 x3 = *(const float4*)(g_H0 + (size_t)c.w * 128 + lane * 4);
        red4(g_F1 + (size_t)r.x * 128 + lane * 4, v.x * x0.x, v.x * x0.y, v.x * x0.z, v.x * x0.w);
        red4(g_F1 + (size_t)r.y * 128 + lane * 4, v.y * x1.x, v.y * x1.y, v.y * x1.z, v.y * x1.w);
        red4(g_F1 + (size_t)r.z * 128 + lane * 4, v.z * x2.x, v.z * x2.y, v.z * x2.z, v.z * x2.w);
        red4(g_F1 + (size_t)r.w * 128 + lane * 4, v.w * x3.x, v.w * x3.y, v.w * x3.z, v.w * x3.w);
    } else {
        for (int e = e0; e < nnz; e++) {
            int r = __ldg(er + e), c = __ldg(ec + e);
            float v = __ldg(ev + e);
            float4 x = *(const float4*)(g_H0 + (size_t)c * 128 + lane * 4);
            red4(g_F1 + (size_t)r * 128 + lane * 4, v * x.x, v * x.y, v * x.z, v * x.w);
        }
    }
}

__global__ void k_spmm64(const int* __restrict__ er, const int* __restrict__ ec,
                         const float* __restrict__ ev, int nnz)
{
    int idx = blockIdx.x * blockDim.x + threadIdx.x;
    int hw = idx >> 4;
    int l = idx & 15;
    int e0 = hw * 4;
    if (e0 >= nnz) return;
    if (e0 + 4 <= nnz) {
        int4 r = *(const int4*)(er + e0);
        int4 c = *(const int4*)(ec + e0);
        float4 v = *(const float4*)(ev + e0);
        float4 x0 = *(const float4*)(g_H1 + (size_t)c.x * 64 + l * 4);
        float4 x1 = *(const float4*)(g_H1 + (size_t)c.y * 64 + l * 4);
        float4 x2 = *(const float4*)(g_H1 + (size_t)c.z * 64 + l * 4);
        float4 x3 = *(const float4*)(g_H1 + (size_t)c.w * 64 + l * 4);
        red4(g_F2 + (size_t)r.x * 64 + l * 4, v.x * x0.x, v.x * x0.y, v.x * x0.z, v.x * x0.w);
        red4(g_F2 + (size_t)r.y * 64 + l * 4, v.y * x1.x, v.y * x1.y, v.y * x1.z, v.y * x1.w);
        red4(g_F2 + (size_t)r.z * 64 + l * 4, v.z * x2.x, v.z * x2.y, v.z * x2.z, v.z * x2.w);
        red4(g_F2 + (size_t)r.w * 64 + l * 4, v.w * x3.x, v.w * x3.y, v.w * x3.z, v.w * x3.w);
    } else {
        for (int e = e0; e < nnz; e++) {
            int r = __ldg(er + e), c = __ldg(ec + e);
            float v = __ldg(ev + e);
            float4 x = *(const float4*)(g_H1 + (size_t)c * 64 + l * 4);
            red4(g_F2 + (size_t)r * 64 + l * 4, v * x.x, v * x.y, v * x.z, v * x.w);
        }
    }
}

// ============================================================================
// Fused MLP head: layer1 (896->64) bf16x3 mma, layers 2/3 FFMA.
// ============================================================================
__global__ __launch_bounds__(256, 2) void k_mlp_mma(
    const int* __restrict__ uIdx, const int* __restrict__ itIdx,
    const float* __restrict__ uE, const float* __restrict__ iE,
    const float* __restrict__ T1b,
    const float* __restrict__ T2W, const float* __restrict__ T2b,
    const float* __restrict__ T3W, const float* __restrict__ T3b,
    float* __restrict__ out, int B)
{
    constexpr int SR = 232;
    constexpr int ABUF = 64 * SR;
    constexpr int OFF_SU = 2 * ABUF * 2;
    constexpr int OFF_SI = OFF_SU + 256;
    constexpr int HSR = 65;
    constexpr int OFF_T2 = 64 * HSR * 4 + 64;
    constexpr int OFF_PART = OFF_T2 + 32 * 64 * 4;
    extern __shared__ __align__(16) char smem[];
    __nv_bfloat16* sA = (__nv_bfloat16*)smem;
    const u32 sbase = smem_u32(smem);
    int* su = (int*)(smem + OFF_SU);
    int* si = (int*)(smem + OFF_SI);

    const int t = threadIdx.x, wid = t >> 5, lane = t & 31;
    const int wm = wid >> 2, wn = wid & 3;
    const int rb = blockIdx.x * 64;

    if (t < 64) {
        int br = rb + t;
        su[t] = (br < B) ? uIdx[br] : 0;
        si[t] = (br < B) ? itIdx[br] : 0;
    }

    float acc[2][2][4];
#pragma unroll
    for (int mt = 0; mt < 2; mt++)
#pragma unroll
        for (int j = 0; j < 2; j++)
#pragma unroll
            for (int q = 0; q < 4; q++) acc[mt][j][q] = 0.f;

    const int arow = lane & 15;
    const int kshift = (lane >> 4) * 8;

    for (int chunk = 0; chunk < 4; chunk++) {
        const int kb = chunk * 224;
        __syncthreads();
#pragma unroll
        for (int it = 0; it < 14; it++) {
            int fid = t + it * 256;
            int r = fid / 56;
            int c4 = (fid % 56) * 4;
            int kg = kb + c4;
            const float* src; int stride, off, rowi;
            if (kg < 256)      { src = uE;   stride = 256; off = kg;       rowi = su[r]; }
            else if (kg < 384) { src = g_F1; stride = 128; off = kg - 256; rowi = su[r]; }
            else if (kg < 448) { src = g_F2; stride = 64;  off = kg - 384; rowi = su[r]; }
            else if (kg < 704) { src = iE;   stride = 256; off = kg - 448; rowi = si[r]; }
            else if (kg < 832) { src = g_F1; stride = 128; off = kg - 704; rowi = si[r] + U_NUM; }
            else               { src = g_F2; stride = 64;  off = kg - 832; rowi = si[r] + U_NUM; }
            float4 v = *(const float4*)(src + (size_t)rowi * stride + off);
            u32 h01, l01, h23, l23;
            split2(v.x, v.y, h01, l01);
            split2(v.z, v.w, h23, l23);
            int so = r * SR + c4;
            *(uint2*)(sA + so)        = make_uint2(h01, h23);
            *(uint2*)(sA + ABUF + so) = make_uint2(l01, l23);
        }
        __syncthreads();

#pragma unroll 2
        for (int ks2 = 0; ks2 < 14; ks2++) {
            const int ks = chunk * 14 + ks2;
            uint4 bw[2];
#pragma unroll
            for (int j = 0; j < 2; j++) {
                int nt = wn * 2 + j;
                bw[j] = __ldg(g_t1f + ((u32)(ks * 8 + nt)) * 32 + lane);
            }
            u32 a[2][2][4];
#pragma unroll
            for (int v = 0; v < 2; v++)
#pragma unroll
                for (int mt = 0; mt < 2; mt++) {
                    int row = wm * 32 + mt * 16 + arow;
                    u32 addr = sbase + (u32)((v * ABUF + row * SR + ks2 * 16 + kshift) * 2);
                    ldm4(a[v][mt], addr);
                }
#pragma unroll
            for (int mt = 0; mt < 2; mt++)
#pragma unroll
                for (int j = 0; j < 2; j++) {
                    mma16816(acc[mt][j], a[0][mt], bw[j].x, bw[j].y);
                    mma16816(acc[mt][j], a[0][mt], bw[j].z, bw[j].w);
                    mma16816(acc[mt][j], a[1][mt], bw[j].x, bw[j].y);
                }
        }
    }
    __syncthreads();

    float* Hs = (float*)smem;
    float* T2s = (float*)(smem + OFF_T2);
    float* part = (float*)(smem + OFF_PART);
    {
        const int rr = wm * 32 + (lane >> 2);
        const int cc = wn * 16 + (lane & 3) * 2;
#pragma unroll
        for (int mt = 0; mt < 2; mt++)
#pragma unroll
            for (int j = 0; j < 2; j++) {
                int c = cc + j * 8;
                float tb0 = __ldg(T1b + c), tb1 = __ldg(T1b + c + 1);
#pragma unroll
                for (int half = 0; half < 2; half++) {
                    int r = rr + mt * 16 + half * 8;
                    Hs[r * HSR + c]     = fmaxf(acc[mt][j][half * 2] + tb0, 0.f);
                    Hs[r * HSR + c + 1] = fmaxf(acc[mt][j][half * 2 + 1] + tb1, 0.f);
                }
            }
    }
#pragma unroll
    for (int i = 0; i < 2; i++) {
        int idx = t + i * 256;
        ((float4*)T2s)[idx] = ((const float4*)T2W)[idx];
    }
    __syncthreads();

    {
        int r = t & 63, g = t >> 6;
        float p = 0.f;
#pragma unroll
        for (int j = 0; j < 8; j++) {
            int c2 = g * 8 + j;
            float s = T2b[c2];
#pragma unroll
            for (int k = 0; k < 64; k++) s += Hs[r * HSR + k] * T2s[c2 * 64 + k];
            p += fmaxf(s, 0.f) * T3W[c2];
        }
        part[g * 64 + r] = p;
    }
    __syncthreads();
    if (t < 64) {
        int br = rb + t;
        if (br < B)
            out[br] = part[t] + part[64 + t] + part[128 + t] + part[192 + t] + T3b[0];
    }
}

// ============================================================================
extern "C" void kernel_launch(void* const* d_in, const int* in_sizes, int n_in,
                              void* d_out, int out_size)
{
    const int*   userIdx = (const int*)d_in[0];
    const int*   itemIdx = (const int*)d_in[1];
    const int*   er      = (const int*)d_in[2];
    const int*   ec      = (const int*)d_in[3];
    const float* ev      = (const float*)d_in[4];
    const float* uE      = (const float*)d_in[5];
    const float* iE      = (const float*)d_in[6];
    const float* W1_0    = (const float*)d_in[7];
    const float* b1_0    = (const float*)d_in[8];
    const float* W2_0    = (const float*)d_in[9];
    const float* b2_0    = (const float*)d_in[10];
    const float* W1_1    = (const float*)d_in[11];
    const float* b1_1    = (const float*)d_in[12];
    const float* W2_1    = (const float*)d_in[13];
    const float* b2_1    = (const float*)d_in[14];
    const float* T1W     = (const float*)d_in[15];
    const float* T1b     = (const float*)d_in[16];
    const float* T2W     = (const float*)d_in[17];
    const float* T2b     = (const float*)d_in[18];
    const float* T3W     = (const float*)d_in[19];
    const float* T3b     = (const float*)d_in[20];
    float* out = (float*)d_out;

    const int B   = in_sizes[0];
    const int nnz = in_sizes[2];

    // gemm0: 256 thr, 2 CTAs/SM, BM=64, CHUNK=128, 2 staged variants
    constexpr int SMEM0 = 2 * 64 * (128 + 8) * 2;    // 34816
    // gemm1: 128 thr, 4 CTAs/SM, BM=64, CHUNK=64, 2 staged variants
    constexpr int SMEM1 = 2 * 64 * (64 + 8) * 2;     // 18432
    constexpr int SMEMM = 2 * 64 * 232 * 2 + 1024;   // 60416
    static bool attr_done = false;
    if (!attr_done) {
        cudaFuncSetAttribute((const void*)k_gemm_mma<256, 2, 64, 128, 256, 128, 0, 2, 4>,
                             cudaFuncAttributeMaxDynamicSharedMemorySize, SMEM0);
        cudaFuncSetAttribute((const void*)k_gemm_mma<128, 4, 64, 64, 128, 64, 1, 2, 2>,
                             cudaFuncAttributeMaxDynamicSharedMemorySize, SMEM1);
        cudaFuncSetAttribute((const void*)k_mlp_mma,
                             cudaFuncAttributeMaxDynamicSharedMemorySize, SMEMM);
        attr_done = true;
    }

    k_prep<<<96, 256>>>(W1_0, W2_0, W1_1, W2_1, T1W);

    k_gemm_mma<256, 2, 64, 128, 256, 128, 0, 2, 4>
        <<<(NTOT + 63) / 64, 256, SMEM0>>>(uE, iE, b1_0, b2_0);

    {
        long long warps = ((long long)nnz + 3) / 4;
        int blocks = (int)((warps * 32 + 255) / 256);
        k_spmm128<<<blocks, 256>>>(er, ec, ev, nnz);
    }

    k_gemm_mma<128, 4, 64, 64, 128, 64, 1, 2, 2>
        <<<(NTOT + 63) / 64, 128, SMEM1>>>(uE, iE, b1_1, b2_1);

    {
        long long hws = ((long long)nnz + 3) / 4;
        int blocks = (int)((hws * 16 + 255) / 256);
        k_spmm64<<<blocks, 256>>>(er, ec, ev, nnz);
    }

    k_mlp_mma<<<(B + 63) / 64, 256, SMEMM>>>(userIdx, itemIdx, uE, iE,
                                             T1b, T2W, T2b, T3W, T3b, out, B);
}